// round 14
// baseline (speedup 1.0000x reference)
#include <cuda_runtime.h>
#include <cuda_bf16.h>
#include <math.h>

// out[d,l]: l==0 -> h0[d]; l>=1 -> sum_k Re(R[k,d]*p[k,d]^(l-1))
// a_t = c1*a_{t-1} - r^2*a_{t-2}; c1 = 2 r cos(theta).
// Fused kernel, SPAN=128 l per block: seed once per pole (p^128 powering, bx
// uniform, bx<16), then packed f32x2 recurrence across four 32-wide register
// sub-chunks carrying state. 4 warps/block, each warp owns 8 poles (2 groups).
// Loops kept rolled (except the 32-step recurrence) to stay inside L1.5 I$.

#define SPAN 128
#define SUB  32
#define NG   2          // pole groups of 4 per warp (8 poles/warp, 4 warps)
#define NW   4          // warps per block

typedef unsigned long long u64p;

__device__ __forceinline__ u64p pk2(float lo, float hi) {
    u64p r; asm("mov.b64 %0, {%1, %2};" : "=l"(r) : "f"(lo), "f"(hi)); return r;
}
__device__ __forceinline__ void upk2(u64p v, float& lo, float& hi) {
    asm("mov.b64 {%0, %1}, %2;" : "=f"(lo), "=f"(hi) : "l"(v));
}
__device__ __forceinline__ u64p mul2(u64p a, u64p b) {
    u64p r; asm("mul.rn.f32x2 %0, %1, %2;" : "=l"(r) : "l"(a), "l"(b)); return r;
}
__device__ __forceinline__ u64p add2(u64p a, u64p b) {
    u64p r; asm("add.rn.f32x2 %0, %1, %2;" : "=l"(r) : "l"(a), "l"(b)); return r;
}
__device__ __forceinline__ u64p fma2(u64p a, u64p b, u64p c) {
    u64p r; asm("fma.rn.f32x2 %0, %1, %2, %3;" : "=l"(r) : "l"(a), "l"(b), "l"(c)); return r;
}

__global__ __launch_bounds__(32 * NW, 4) void lh_fused_kernel(
    const float* __restrict__ rr, const float* __restrict__ th,
    const float* __restrict__ Rre, const float* __restrict__ Rim,
    const float* __restrict__ h0, float* __restrict__ out,
    int D, int L, int K)
{
    const int bx   = blockIdx.x;          // l-span index (uniform exponent)
    const int l0   = bx * SPAN;
    const int d0   = blockIdx.y * 32;
    const int lane = threadIdx.x & 31;
    const int wid  = threadIdx.x >> 5;
    const int d    = d0 + lane;

    __shared__ float tile[NW][32][SUB + 1];

    const int kbeg = wid * (K / NW);      // 8 poles per warp

    // ---- persistent per-group packed state (seed once for the whole SPAN) --
    u64p C1[NG][2], N2[NG][2], A0[NG][2], A1[NG][2];

    for (int g = 0; g < NG; ++g) {        // rolled: small I$ footprint
        float sa0[4], sa1[4], sc1[4], sn2[4];
#pragma unroll
        for (int u = 0; u < 4; ++u) {     // unrolled: 4-way ILP in seeding
            const int idx = (kbeg + 4 * g + u) * D + d;
            const float r  = rr[idx];
            const float t_ = th[idx];
            const float Ar = Rre[idx];
            const float Ai = Rim[idx];

            float st, ct;
            sincosf(t_, &st, &ct);
            const float pre = r * ct;            // Re(p)
            const float pim = r * st;            // Im(p)
            sc1[u] = 2.0f * pre;
            sn2[u] = -(r * r);

            // q = p^SPAN (7 complex squarings for SPAN=128)
            float qr = pre, qi = pim;
#pragma unroll
            for (int s = 0; s < 7; ++s) {
                float t1 = qi * qi;
                float nr = fmaf(qr, qr, -t1);
                float t2 = qr * qi;
                qi = t2 + t2;
                qr = nr;
            }
            // w = q^bx (binary powering; bx < 16, uniform per block)
            float wr = 1.0f, wi = 0.0f;
            float br = qr, bi = qi;
            int e = bx;
#pragma unroll
            for (int b = 0; b < 4; ++b) {
                if (e & 1) {
                    float nr = fmaf(wr, br, -wi * bi);
                    float ni = fmaf(wr, bi,  wi * br);
                    wr = nr; wi = ni;
                }
                e >>= 1;
                float t1 = bi * bi;
                float nr = fmaf(br, br, -t1);
                float t2 = br * bi;
                bi = t2 + t2;
                br = nr;
            }
            // a1 = Re(R w) = a(l0);  a0 = Re(R w conj(p))/r^2 = a(l0-1)
            float zr = fmaf(Ar, wr, -Ai * wi);
            float zi = fmaf(Ar, wi,  Ai * wr);
            sa1[u] = zr;
            sa0[u] = __fdividef(fmaf(zr, pre, zi * pim), r * r);
        }
        C1[g][0] = pk2(sc1[0], sc1[1]);  C1[g][1] = pk2(sc1[2], sc1[3]);
        N2[g][0] = pk2(sn2[0], sn2[1]);  N2[g][1] = pk2(sn2[2], sn2[3]);
        A0[g][0] = pk2(sa0[0], sa0[1]);  A0[g][1] = pk2(sa0[2], sa0[3]);
        A1[g][0] = pk2(sa1[0], sa1[1]);  A1[g][1] = pk2(sa1[2], sa1[3]);
    }

    const u64p z = pk2(0.0f, 0.0f);
    u64p acc[SUB];

    for (int sub = 0; sub < SPAN / SUB; ++sub) {   // rolled
#pragma unroll
        for (int i = 0; i < SUB; ++i) acc[i] = z;

        for (int g = 0; g < NG; ++g) {             // rolled
            u64p a00 = A0[g][0], a01 = A0[g][1];
            u64p a10 = A1[g][0], a11 = A1[g][1];
            const u64p c10 = C1[g][0], c11 = C1[g][1];
            const u64p n20 = N2[g][0], n21 = N2[g][1];
            u64p S = z;

            if (sub == 0) {
                // first two outputs come straight from the seeds
                acc[0] = add2(acc[0], add2(a00, a01));
                acc[1] = add2(acc[1], add2(a10, a11));
#pragma unroll
                for (int i = 2; i < SUB; ++i) {
                    u64p m0 = mul2(n20, a00);
                    u64p m1 = mul2(n21, a01);
                    u64p n0 = fma2(c10, a10, m0);
                    u64p n1 = fma2(c11, a11, m1);
                    if (i > 2) acc[i - 1] = add2(acc[i - 1], S);
                    S = add2(n0, n1);
                    a00 = a10; a10 = n0;
                    a01 = a11; a11 = n1;
                }
            } else {
                // continue the chain: 32 fresh recurrence steps
#pragma unroll
                for (int i = 0; i < SUB; ++i) {
                    u64p m0 = mul2(n20, a00);
                    u64p m1 = mul2(n21, a01);
                    u64p n0 = fma2(c10, a10, m0);
                    u64p n1 = fma2(c11, a11, m1);
                    if (i > 0) acc[i - 1] = add2(acc[i - 1], S);
                    S = add2(n0, n1);
                    a00 = a10; a10 = n0;
                    a01 = a11; a11 = n1;
                }
            }
            acc[SUB - 1] = add2(acc[SUB - 1], S);

            A0[g][0] = a00; A0[g][1] = a01;
            A1[g][0] = a10; A1[g][1] = a11;
        }

        // ---- flush this sub-chunk (combine NW warps through shared) ----
#pragma unroll
        for (int i = 0; i < SUB; ++i) {
            float lo, hi;
            upk2(acc[i], lo, hi);
            tile[wid][lane][i] = lo + hi;
        }
        __syncthreads();

        const int lbase = l0 + sub * SUB;
        const int total = 32 * SUB;
        for (int j = threadIdx.x; j < total; j += 32 * NW) {
            int row = j >> 5;           // / SUB
            int col = j & (SUB - 1);    // % SUB
            int l = lbase + col;
            float v = (tile[0][row][col] + tile[1][row][col])
                    + (tile[2][row][col] + tile[3][row][col]);
            if (l == 0) v = h0[d0 + row];
            if (l < L) out[(size_t)(d0 + row) * L + l] = v;
        }
        __syncthreads();
    }
}

extern "C" void kernel_launch(void* const* d_in, const int* in_sizes, int n_in,
                              void* d_out, int out_size)
{
    const float* rr  = (const float*)d_in[0];
    const float* th  = (const float*)d_in[1];
    const float* Rre = (const float*)d_in[2];
    const float* Rim = (const float*)d_in[3];
    const float* h0  = (const float*)d_in[4];
    float* out = (float*)d_out;

    const int D = in_sizes[4];
    const int K = in_sizes[0] / D;
    const int L = out_size / D;
    const int NBX = (L + SPAN - 1) / SPAN;

    dim3 grid(NBX, D / 32);
    lh_fused_kernel<<<grid, 32 * NW>>>(rr, th, Rre, Rim, h0, out, D, L, K);
}